// round 9
// baseline (speedup 1.0000x reference)
#include <cuda_runtime.h>
#include <cuda_bf16.h>
#include <cstdint>
#include <cstddef>

#define N_NODES   100000
#define NTOT      50000     // batch
#define FEAT      256
#define KDIM      512       // feat + embed
#define MDIM      256       // embed (output rows)
#define NSAMP     25
#define NANFILL   0.01f

// ---------------- device scratch (no allocations allowed) ----------------
__device__ __nv_bfloat16 g_Ch[(size_t)NTOT * KDIM];   // combined, bf16 hi
__device__ __nv_bfloat16 g_Cl[(size_t)NTOT * KDIM];   // combined, bf16 lo
__device__ __nv_bfloat16 g_Wh[(size_t)MDIM * KDIM];
__device__ __nv_bfloat16 g_Wl[(size_t)MDIM * KDIM];
__device__ int g_idx64;   // 1 if index buffers are int64, 0 if int32

// ---------------- helpers ----------------
__device__ __forceinline__ unsigned short f2bf(float x) {
    __nv_bfloat16 b = __float2bfloat16(x);
    return reinterpret_cast<unsigned short&>(b);
}
__device__ __forceinline__ float bf2f(unsigned short u) {
    __nv_bfloat16 b = reinterpret_cast<__nv_bfloat16&>(u);
    return __bfloat162float(b);
}

// split x into hi (bf16 round-nearest) and lo (residual rounded to bf16)
__device__ __forceinline__ void split1(float x, unsigned short& h, unsigned short& l) {
    h = f2bf(x);
    l = f2bf(x - bf2f(h));
}

__device__ __forceinline__ void split_store4(float4 v, size_t idx) {
    ushort4 H, L;
    split1(v.x, H.x, L.x);
    split1(v.y, H.y, L.y);
    split1(v.z, H.z, L.z);
    split1(v.w, H.w, L.w);
    *reinterpret_cast<ushort4*>(&g_Ch[idx]) = H;
    *reinterpret_cast<ushort4*>(&g_Cl[idx]) = L;
}

__device__ __forceinline__ int clampi(int v) {
    v = v < 0 ? 0 : v;
    return v >= N_NODES ? N_NODES - 1 : v;
}

// ---------------- kernel 0a: detect index dtype (int64 vs int32) ----------------
// JAX with x64 disabled silently downgrades jnp.int64 -> int32; detect at runtime.
// Reads only the first 4KB of the neigh_idx buffer (safe under either dtype).
__global__ void detect_kernel(const void* __restrict__ nidx_v) {
    if (threadIdx.x == 0) {
        const long long* p = (const long long*)nidx_v;
        int ok = 1;
        for (int i = 0; i < 512; i++) {
            long long v = p[i];
            if (v < 0 || v >= (long long)N_NODES) { ok = 0; break; }
        }
        g_idx64 = ok;
    }
}

// ---------------- kernel 0b: split W into bf16 hi/lo ----------------
__global__ void wsplit_kernel(const float* __restrict__ w) {
    int i = blockIdx.x * blockDim.x + threadIdx.x;
    if (i < MDIM * KDIM) {
        unsigned short h, l;
        split1(w[i], h, l);
        g_Wh[i] = reinterpret_cast<__nv_bfloat16&>(h);
        g_Wl[i] = reinterpret_cast<__nv_bfloat16&>(l);
    }
}

// ---------------- kernel 1: gather self + mean(neighbors) -> split bf16 ----------------
// one warp per batch node; 8 warps / block
__global__ void gather_kernel(const float4* __restrict__ feat4,
                              const void* __restrict__ nodes_v,
                              const void* __restrict__ nidx_v) {
    __shared__ int sIdx[8][32];
    const int warp = threadIdx.x >> 5;
    const int lane = threadIdx.x & 31;
    const int b = blockIdx.x * 8 + warp;
    if (b >= NTOT) return;

    const int is64 = g_idx64;

    if (lane < NSAMP) {
        const size_t off = (size_t)b * NSAMP + lane;
        int v = is64 ? (int)((const long long*)nidx_v)[off]
                     : ((const int*)nidx_v)[off];
        sIdx[warp][lane] = clampi(v);
    }
    int node = is64 ? (int)((const long long*)nodes_v)[b]
                    : ((const int*)nodes_v)[b];
    node = clampi(node);
    __syncwarp();

    // self features -> C[b, 0:256]
    const float4* srow = feat4 + (size_t)node * (FEAT / 4);
    {
        float4 v0 = __ldg(srow + lane);
        float4 v1 = __ldg(srow + lane + 32);
        split_store4(v0, (size_t)b * KDIM + (size_t)lane * 4);
        split_store4(v1, (size_t)b * KDIM + (size_t)(lane + 32) * 4);
    }

    // neighbor mean -> C[b, 256:512]
    float4 a0 = make_float4(0.f, 0.f, 0.f, 0.f);
    float4 a1 = make_float4(0.f, 0.f, 0.f, 0.f);
#pragma unroll
    for (int j = 0; j < NSAMP; j++) {
        const float4* r = feat4 + (size_t)sIdx[warp][j] * (FEAT / 4);
        float4 x = __ldg(r + lane);
        float4 y = __ldg(r + lane + 32);
        a0.x += x.x; a0.y += x.y; a0.z += x.z; a0.w += x.w;
        a1.x += y.x; a1.y += y.y; a1.z += y.z; a1.w += y.w;
    }
    const float inv = 1.0f / (float)NSAMP;
    a0.x *= inv; a0.y *= inv; a0.z *= inv; a0.w *= inv;
    a1.x *= inv; a1.y *= inv; a1.z *= inv; a1.w *= inv;
    // nan fill (no-op for this data, but match reference semantics)
    a0.x = isnan(a0.x) ? NANFILL : a0.x;  a0.y = isnan(a0.y) ? NANFILL : a0.y;
    a0.z = isnan(a0.z) ? NANFILL : a0.z;  a0.w = isnan(a0.w) ? NANFILL : a0.w;
    a1.x = isnan(a1.x) ? NANFILL : a1.x;  a1.y = isnan(a1.y) ? NANFILL : a1.y;
    a1.z = isnan(a1.z) ? NANFILL : a1.z;  a1.w = isnan(a1.w) ? NANFILL : a1.w;

    split_store4(a0, (size_t)b * KDIM + FEAT + (size_t)lane * 4);
    split_store4(a1, (size_t)b * KDIM + FEAT + (size_t)(lane + 32) * 4);
}

// ---------------- kernel 2: split-bf16 GEMM + ReLU ----------------
// out[m, n] = relu( sum_k W[m,k] * C[n,k] ), M=256, N=50000, K=512
// D = Wh*Ch + Wh*Cl + Wl*Ch  (3x bf16 mma, fp32 accumulate)
#define BM 128
#define BN 128
#define BK 32
#define SPAD 40   // bf16 elements per smem row (80 bytes, 16B-aligned stride, conflict-free LDSM)

__device__ __forceinline__ void ldsm4(uint32_t& r0, uint32_t& r1, uint32_t& r2, uint32_t& r3,
                                      const void* p) {
    uint32_t a = (uint32_t)__cvta_generic_to_shared(p);
    asm volatile("ldmatrix.sync.aligned.m8n8.x4.shared.b16 {%0,%1,%2,%3}, [%4];\n"
                 : "=r"(r0), "=r"(r1), "=r"(r2), "=r"(r3) : "r"(a));
}
__device__ __forceinline__ void ldsm2(uint32_t& r0, uint32_t& r1, const void* p) {
    uint32_t a = (uint32_t)__cvta_generic_to_shared(p);
    asm volatile("ldmatrix.sync.aligned.m8n8.x2.shared.b16 {%0,%1}, [%2];\n"
                 : "=r"(r0), "=r"(r1) : "r"(a));
}
__device__ __forceinline__ void mma16816(float* d, const uint32_t* a, const uint32_t* b) {
    asm volatile(
        "mma.sync.aligned.m16n8k16.row.col.f32.bf16.bf16.f32 "
        "{%0,%1,%2,%3}, {%4,%5,%6,%7}, {%8,%9}, {%0,%1,%2,%3};\n"
        : "+f"(d[0]), "+f"(d[1]), "+f"(d[2]), "+f"(d[3])
        : "r"(a[0]), "r"(a[1]), "r"(a[2]), "r"(a[3]), "r"(b[0]), "r"(b[1]));
}

__global__ __launch_bounds__(256, 2) void gemm_kernel(float* __restrict__ out) {
    __shared__ __nv_bfloat16 sAh[BM][SPAD];
    __shared__ __nv_bfloat16 sAl[BM][SPAD];
    __shared__ __nv_bfloat16 sBh[BN][SPAD];
    __shared__ __nv_bfloat16 sBl[BN][SPAD];

    const int tid = threadIdx.x;
    const int warp = tid >> 5;
    const int lane = tid & 31;
    const int wm = warp >> 2;   // 0..1  (64 M-rows per warp)
    const int wn = warp & 3;    // 0..3  (32 N-cols per warp)
    const int m0 = blockIdx.y * BM;
    const int n0 = blockIdx.x * BN;

    float acc[4][4][4];
#pragma unroll
    for (int i = 0; i < 4; i++)
#pragma unroll
        for (int j = 0; j < 4; j++)
#pragma unroll
            for (int k = 0; k < 4; k++) acc[i][j][k] = 0.f;

    for (int kt = 0; kt < KDIM; kt += BK) {
        // stage global loads (issued before the barrier to overlap with other warps)
        uint4 vA[2], vAl[2], vB[2], vBl[2];
#pragma unroll
        for (int t = 0; t < 2; t++) {
            const int ch = tid + t * 256;
            const int row = ch >> 2;
            const int seg = ch & 3;
            const size_t aoff = (size_t)(m0 + row) * KDIM + kt + seg * 8;
            vA[t]  = *reinterpret_cast<const uint4*>(&g_Wh[aoff]);
            vAl[t] = *reinterpret_cast<const uint4*>(&g_Wl[aoff]);
            const int n = n0 + row;
            if (n < NTOT) {
                const size_t boff = (size_t)n * KDIM + kt + seg * 8;
                vB[t]  = *reinterpret_cast<const uint4*>(&g_Ch[boff]);
                vBl[t] = *reinterpret_cast<const uint4*>(&g_Cl[boff]);
            } else {
                vB[t]  = make_uint4(0u, 0u, 0u, 0u);
                vBl[t] = make_uint4(0u, 0u, 0u, 0u);
            }
        }
        __syncthreads();
#pragma unroll
        for (int t = 0; t < 2; t++) {
            const int ch = tid + t * 256;
            const int row = ch >> 2;
            const int seg = ch & 3;
            *reinterpret_cast<uint4*>(&sAh[row][seg * 8]) = vA[t];
            *reinterpret_cast<uint4*>(&sAl[row][seg * 8]) = vAl[t];
            *reinterpret_cast<uint4*>(&sBh[row][seg * 8]) = vB[t];
            *reinterpret_cast<uint4*>(&sBl[row][seg * 8]) = vBl[t];
        }
        __syncthreads();

#pragma unroll
        for (int ks = 0; ks < BK; ks += 16) {
            uint32_t bh[4][2], bl[4][2];
#pragma unroll
            for (int ni = 0; ni < 4; ni++) {
                const int r = wn * 32 + ni * 8 + (lane & 7);
                const int c = ks + ((lane >> 3) & 1) * 8;
                ldsm2(bh[ni][0], bh[ni][1], &sBh[r][c]);
                ldsm2(bl[ni][0], bl[ni][1], &sBl[r][c]);
            }
#pragma unroll
            for (int mi = 0; mi < 4; mi++) {
                uint32_t ah[4], al[4];
                const int r = wm * 64 + mi * 16 + (lane & 15);
                const int c = ks + (lane >> 4) * 8;
                ldsm4(ah[0], ah[1], ah[2], ah[3], &sAh[r][c]);
                ldsm4(al[0], al[1], al[2], al[3], &sAl[r][c]);
#pragma unroll
                for (int ni = 0; ni < 4; ni++) {
                    mma16816(acc[mi][ni], ah, bh[ni]);   // hi*hi
                    mma16816(acc[mi][ni], ah, bl[ni]);   // hi*lo
                    mma16816(acc[mi][ni], al, bh[ni]);   // lo*hi
                }
            }
        }
    }

    // epilogue: relu + store (float2, coalesced pairs)
#pragma unroll
    for (int mi = 0; mi < 4; mi++) {
#pragma unroll
        for (int ni = 0; ni < 4; ni++) {
            const int m = m0 + wm * 64 + mi * 16 + (lane >> 2);
            const int n = n0 + wn * 32 + ni * 8 + (lane & 3) * 2;
            if (n < NTOT) {
                float2 v0, v1;
                v0.x = fmaxf(acc[mi][ni][0], 0.f);
                v0.y = fmaxf(acc[mi][ni][1], 0.f);
                v1.x = fmaxf(acc[mi][ni][2], 0.f);
                v1.y = fmaxf(acc[mi][ni][3], 0.f);
                *reinterpret_cast<float2*>(&out[(size_t)m * NTOT + n]) = v0;
                *reinterpret_cast<float2*>(&out[(size_t)(m + 8) * NTOT + n]) = v1;
            }
        }
    }
}

// ---------------- launch ----------------
extern "C" void kernel_launch(void* const* d_in, const int* in_sizes, int n_in,
                              void* d_out, int out_size) {
    const float* features = (const float*)d_in[0];   // [100000, 256] f32
    const float* weight   = (const float*)d_in[1];   // [256, 512] f32
    const void*  nodes    = d_in[2];                 // [50000] int32 or int64
    const void*  nidx     = d_in[3];                 // [50000, 25] int32 or int64
    float* out            = (float*)d_out;           // [256, 50000] f32

    detect_kernel<<<1, 32>>>(nidx);
    wsplit_kernel<<<(MDIM * KDIM + 255) / 256, 256>>>(weight);
    gather_kernel<<<(NTOT + 7) / 8, 256>>>(
        reinterpret_cast<const float4*>(features), nodes, nidx);
    dim3 grid((NTOT + BN - 1) / BN, MDIM / BM);
    gemm_kernel<<<grid, 256>>>(out);
}

// round 11
// speedup vs baseline: 1.0624x; 1.0624x over previous
#include <cuda_runtime.h>
#include <cuda_bf16.h>
#include <cstdint>
#include <cstddef>

#define N_NODES   100000
#define NTOT      50000     // batch
#define NPAD      50176     // NTOT padded to multiple of 128 (tile overreach stays in-bounds)
#define FEAT      256
#define KDIM      512       // feat + embed
#define MDIM      256       // embed (output rows)
#define NSAMP     25
#define NANFILL   0.01f

// ---------------- device scratch (no allocations allowed) ----------------
// zero-initialized at module load; rows [NTOT, NPAD) are never written -> stay 0
__device__ __nv_bfloat16 g_Ch[(size_t)NPAD * KDIM];   // combined, bf16 hi
__device__ __nv_bfloat16 g_Cl[(size_t)NPAD * KDIM];   // combined, bf16 lo
__device__ __nv_bfloat16 g_Wh[(size_t)MDIM * KDIM];
__device__ __nv_bfloat16 g_Wl[(size_t)MDIM * KDIM];
__device__ int g_idx64;   // 1 if index buffers are int64, 0 if int32

// ---------------- scalar helpers ----------------
__device__ __forceinline__ unsigned short f2bf(float x) {
    __nv_bfloat16 b = __float2bfloat16(x);
    return reinterpret_cast<unsigned short&>(b);
}
__device__ __forceinline__ float bf2f(unsigned short u) {
    __nv_bfloat16 b = reinterpret_cast<__nv_bfloat16&>(u);
    return __bfloat162float(b);
}
__device__ __forceinline__ void split1(float x, unsigned short& h, unsigned short& l) {
    h = f2bf(x);
    l = f2bf(x - bf2f(h));
}
__device__ __forceinline__ void split_store4(float4 v, size_t idx) {
    ushort4 H, L;
    split1(v.x, H.x, L.x);
    split1(v.y, H.y, L.y);
    split1(v.z, H.z, L.z);
    split1(v.w, H.w, L.w);
    *reinterpret_cast<ushort4*>(&g_Ch[idx]) = H;
    *reinterpret_cast<ushort4*>(&g_Cl[idx]) = L;
}
__device__ __forceinline__ int clampi(int v) {
    v = v < 0 ? 0 : v;
    return v >= N_NODES ? N_NODES - 1 : v;
}

// ---------------- kernel 0a: detect index dtype (int64 vs int32) ----------------
// JAX with x64 disabled silently downgrades jnp.int64 -> int32; detect at runtime.
__global__ void detect_kernel(const void* __restrict__ nidx_v) {
    if (threadIdx.x == 0) {
        const long long* p = (const long long*)nidx_v;
        int ok = 1;
        for (int i = 0; i < 512; i++) {
            long long v = p[i];
            if (v < 0 || v >= (long long)N_NODES) { ok = 0; break; }
        }
        g_idx64 = ok;
    }
}

// ---------------- kernel 0b: split W into bf16 hi/lo ----------------
__global__ void wsplit_kernel(const float* __restrict__ w) {
    int i = blockIdx.x * blockDim.x + threadIdx.x;
    if (i < MDIM * KDIM) {
        unsigned short h, l;
        split1(w[i], h, l);
        g_Wh[i] = reinterpret_cast<__nv_bfloat16&>(h);
        g_Wl[i] = reinterpret_cast<__nv_bfloat16&>(l);
    }
}

// ---------------- kernel 1: gather self + mean(neighbors) -> split bf16 ----------------
// one warp per batch node; 8 warps / block (at the L2 roofline already)
__global__ void gather_kernel(const float4* __restrict__ feat4,
                              const void* __restrict__ nodes_v,
                              const void* __restrict__ nidx_v) {
    __shared__ int sIdx[8][32];
    const int warp = threadIdx.x >> 5;
    const int lane = threadIdx.x & 31;
    const int b = blockIdx.x * 8 + warp;
    if (b >= NTOT) return;

    const int is64 = g_idx64;

    if (lane < NSAMP) {
        const size_t off = (size_t)b * NSAMP + lane;
        int v = is64 ? (int)((const long long*)nidx_v)[off]
                     : ((const int*)nidx_v)[off];
        sIdx[warp][lane] = clampi(v);
    }
    int node = is64 ? (int)((const long long*)nodes_v)[b]
                    : ((const int*)nodes_v)[b];
    node = clampi(node);
    __syncwarp();

    const float4* srow = feat4 + (size_t)node * (FEAT / 4);
    {
        float4 v0 = __ldg(srow + lane);
        float4 v1 = __ldg(srow + lane + 32);
        split_store4(v0, (size_t)b * KDIM + (size_t)lane * 4);
        split_store4(v1, (size_t)b * KDIM + (size_t)(lane + 32) * 4);
    }

    float4 a0 = make_float4(0.f, 0.f, 0.f, 0.f);
    float4 a1 = make_float4(0.f, 0.f, 0.f, 0.f);
#pragma unroll
    for (int j = 0; j < NSAMP; j++) {
        const float4* r = feat4 + (size_t)sIdx[warp][j] * (FEAT / 4);
        float4 x = __ldg(r + lane);
        float4 y = __ldg(r + lane + 32);
        a0.x += x.x; a0.y += x.y; a0.z += x.z; a0.w += x.w;
        a1.x += y.x; a1.y += y.y; a1.z += y.z; a1.w += y.w;
    }
    const float inv = 1.0f / (float)NSAMP;
    a0.x *= inv; a0.y *= inv; a0.z *= inv; a0.w *= inv;
    a1.x *= inv; a1.y *= inv; a1.z *= inv; a1.w *= inv;
    a0.x = isnan(a0.x) ? NANFILL : a0.x;  a0.y = isnan(a0.y) ? NANFILL : a0.y;
    a0.z = isnan(a0.z) ? NANFILL : a0.z;  a0.w = isnan(a0.w) ? NANFILL : a0.w;
    a1.x = isnan(a1.x) ? NANFILL : a1.x;  a1.y = isnan(a1.y) ? NANFILL : a1.y;
    a1.z = isnan(a1.z) ? NANFILL : a1.z;  a1.w = isnan(a1.w) ? NANFILL : a1.w;

    split_store4(a0, (size_t)b * KDIM + FEAT + (size_t)lane * 4);
    split_store4(a1, (size_t)b * KDIM + FEAT + (size_t)(lane + 32) * 4);
}

// ---------------- kernel 2: split-bf16 GEMM + ReLU, cp.async double-buffered ----------------
// out[m, n] = relu( sum_k W[m,k] * C[n,k] ), M=256, N=50000, K=512
// D = Wh*Ch + Wh*Cl + Wl*Ch  (3x bf16 mma, fp32 accumulate)
#define BM 128
#define BN 128
#define BK 32
#define SPAD 40   // bf16 elements per smem row (80B stride, 16B aligned, conflict-free LDSM)
#define NKT (KDIM / BK)                // 16
#define ARR_ELEMS (BM * SPAD)          // 5120 elems per array
#define STG_ELEMS (4 * ARR_ELEMS)      // Ah | Al | Bh | Bl
#define GEMM_SMEM (2 * STG_ELEMS * 2)  // bytes: 81920

__device__ __forceinline__ void cp16(uint32_t smem_addr, const void* gptr) {
    asm volatile("cp.async.cg.shared.global [%0], [%1], 16;\n"
                 :: "r"(smem_addr), "l"(gptr) : "memory");
}
__device__ __forceinline__ void cp_commit() {
    asm volatile("cp.async.commit_group;\n" ::: "memory");
}
__device__ __forceinline__ void cp_wait1() {
    asm volatile("cp.async.wait_group 1;\n" ::: "memory");
}
__device__ __forceinline__ void cp_wait0() {
    asm volatile("cp.async.wait_group 0;\n" ::: "memory");
}

__device__ __forceinline__ void ldsm4(uint32_t& r0, uint32_t& r1, uint32_t& r2, uint32_t& r3,
                                      const void* p) {
    uint32_t a = (uint32_t)__cvta_generic_to_shared(p);
    asm volatile("ldmatrix.sync.aligned.m8n8.x4.shared.b16 {%0,%1,%2,%3}, [%4];\n"
                 : "=r"(r0), "=r"(r1), "=r"(r2), "=r"(r3) : "r"(a));
}
__device__ __forceinline__ void ldsm2(uint32_t& r0, uint32_t& r1, const void* p) {
    uint32_t a = (uint32_t)__cvta_generic_to_shared(p);
    asm volatile("ldmatrix.sync.aligned.m8n8.x2.shared.b16 {%0,%1}, [%2];\n"
                 : "=r"(r0), "=r"(r1) : "r"(a));
}
__device__ __forceinline__ void mma16816(float* d, const uint32_t* a, const uint32_t* b) {
    asm volatile(
        "mma.sync.aligned.m16n8k16.row.col.f32.bf16.bf16.f32 "
        "{%0,%1,%2,%3}, {%4,%5,%6,%7}, {%8,%9}, {%0,%1,%2,%3};\n"
        : "+f"(d[0]), "+f"(d[1]), "+f"(d[2]), "+f"(d[3])
        : "r"(a[0]), "r"(a[1]), "r"(a[2]), "r"(a[3]), "r"(b[0]), "r"(b[1]));
}

// issue cp.async for one kt into one stage (8 x 16B per thread)
__device__ __forceinline__ void load_stage(__nv_bfloat16* base, int kt, int tid,
                                           int m0, int n0) {
    const int kof = kt * BK;
#pragma unroll
    for (int i = tid; i < 512; i += 256) {     // 128 rows x 4 segs
        const int row = i >> 2;
        const int col = (i & 3) * 8;
        const uint32_t dst =
            (uint32_t)__cvta_generic_to_shared(base + row * SPAD + col);
        const size_t aoff = (size_t)(m0 + row) * KDIM + kof + col;
        const size_t boff = (size_t)(n0 + row) * KDIM + kof + col;  // padded, no guard
        cp16(dst,                       &g_Wh[aoff]);
        cp16(dst + 1 * ARR_ELEMS * 2,   &g_Wl[aoff]);
        cp16(dst + 2 * ARR_ELEMS * 2,   &g_Ch[boff]);
        cp16(dst + 3 * ARR_ELEMS * 2,   &g_Cl[boff]);
    }
}

__global__ __launch_bounds__(256, 2) void gemm_kernel(float* __restrict__ out) {
    extern __shared__ __nv_bfloat16 smem[];

    const int tid = threadIdx.x;
    const int warp = tid >> 5;
    const int lane = tid & 31;
    const int wm = warp >> 2;   // 0..1  (64 M-rows per warp)
    const int wn = warp & 3;    // 0..3  (32 N-cols per warp)
    const int m0 = blockIdx.y * BM;
    const int n0 = blockIdx.x * BN;

    float acc[4][4][4];
#pragma unroll
    for (int i = 0; i < 4; i++)
#pragma unroll
        for (int j = 0; j < 4; j++)
#pragma unroll
            for (int k = 0; k < 4; k++) acc[i][j][k] = 0.f;

    // prologue: stage 0 <- kt 0
    load_stage(smem, 0, tid, m0, n0);
    cp_commit();

    for (int kt = 0; kt < NKT; kt++) {
        const int st = kt & 1;
        // issue next tile into the other stage, then drain the current one
        if (kt + 1 < NKT) {
            load_stage(smem + (st ^ 1) * STG_ELEMS, kt + 1, tid, m0, n0);
            cp_commit();
            cp_wait1();
        } else {
            cp_wait0();
        }
        __syncthreads();

        const __nv_bfloat16* sAh = smem + st * STG_ELEMS;
        const __nv_bfloat16* sAl = sAh + ARR_ELEMS;
        const __nv_bfloat16* sBh = sAh + 2 * ARR_ELEMS;
        const __nv_bfloat16* sBl = sAh + 3 * ARR_ELEMS;

#pragma unroll
        for (int ks = 0; ks < BK; ks += 16) {
            uint32_t bh[4][2], bl[4][2];
#pragma unroll
            for (int ni = 0; ni < 4; ni++) {
                const int r = wn * 32 + ni * 8 + (lane & 7);
                const int c = ks + ((lane >> 3) & 1) * 8;
                ldsm2(bh[ni][0], bh[ni][1], &sBh[r * SPAD + c]);
                ldsm2(bl[ni][0], bl[ni][1], &sBl[r * SPAD + c]);
            }
#pragma unroll
            for (int mi = 0; mi < 4; mi++) {
                uint32_t ah[4], al[4];
                const int r = wm * 64 + mi * 16 + (lane & 15);
                const int c = ks + (lane >> 4) * 8;
                ldsm4(ah[0], ah[1], ah[2], ah[3], &sAh[r * SPAD + c]);
                ldsm4(al[0], al[1], al[2], al[3], &sAl[r * SPAD + c]);
#pragma unroll
                for (int ni = 0; ni < 4; ni++) {
                    mma16816(acc[mi][ni], ah, bh[ni]);   // hi*hi
                    mma16816(acc[mi][ni], ah, bl[ni]);   // hi*lo
                    mma16816(acc[mi][ni], al, bh[ni]);   // lo*hi
                }
            }
        }
        __syncthreads();   // all warps done with stage st before it is overwritten
    }

    // epilogue: relu + store (float2, coalesced pairs)
#pragma unroll
    for (int mi = 0; mi < 4; mi++) {
#pragma unroll
        for (int ni = 0; ni < 4; ni++) {
            const int m = m0 + wm * 64 + mi * 16 + (lane >> 2);
            const int n = n0 + wn * 32 + ni * 8 + (lane & 3) * 2;
            if (n < NTOT) {
                float2 v0, v1;
                v0.x = fmaxf(acc[mi][ni][0], 0.f);
                v0.y = fmaxf(acc[mi][ni][1], 0.f);
                v1.x = fmaxf(acc[mi][ni][2], 0.f);
                v1.y = fmaxf(acc[mi][ni][3], 0.f);
                *reinterpret_cast<float2*>(&out[(size_t)m * NTOT + n]) = v0;
                *reinterpret_cast<float2*>(&out[(size_t)(m + 8) * NTOT + n]) = v1;
            }
        }
    }
}

// ---------------- launch ----------------
extern "C" void kernel_launch(void* const* d_in, const int* in_sizes, int n_in,
                              void* d_out, int out_size) {
    const float* features = (const float*)d_in[0];   // [100000, 256] f32
    const float* weight   = (const float*)d_in[1];   // [256, 512] f32
    const void*  nodes    = d_in[2];                 // [50000] int32 or int64
    const void*  nidx     = d_in[3];                 // [50000, 25] int32 or int64
    float* out            = (float*)d_out;           // [256, 50000] f32

    // idempotent, no allocation, graph-capture safe
    cudaFuncSetAttribute(gemm_kernel, cudaFuncAttributeMaxDynamicSharedMemorySize,
                         GEMM_SMEM);

    detect_kernel<<<1, 32>>>(nidx);
    wsplit_kernel<<<(MDIM * KDIM + 255) / 256, 256>>>(weight);
    gather_kernel<<<(NTOT + 7) / 8, 256>>>(
        reinterpret_cast<const float4*>(features), nodes, nidx);
    dim3 grid((NTOT + BN - 1) / BN, MDIM / BM);
    gemm_kernel<<<grid, 256, GEMM_SMEM>>>(out);
}